// round 16
// baseline (speedup 1.0000x reference)
#include <cuda_runtime.h>
#include <cuda_fp16.h>
#include <cstdint>

// 3-term fp16-split GEMM. Main term Ah*Bh in f32-acc MMA; correction terms
// Al*Bh + Ah*Bl in a chained f16-acc MMA (2x rate), folded in at epilogue.
// 512-thread CTAs, 16 warps, 32x32 warp tiles.

#define A_RS 12
#define B_RS 136
#define STG_W (2 * 128 * A_RS + 2 * 8 * B_RS)   // 5248 words
#define SMEM_BYTES (3 * STG_W * 4)               // 62976

// A-role: [plane0|plane1], rows m, K/2 words/row
__device__ uint32_t eUt  [2u * 1572864u];   // [z][i][512]  zs=524288
__device__ uint32_t eUcat[2u * 1572864u];   // [i][1536]
__device__ uint32_t eAGG [2u * 12582912u];  // zs=4194304 ([b*1024+i][Din/2])
__device__ uint32_t eM1  [2u * 12582912u];  // [m'][64]
// B-role: word rows kp=(k>>4)*8+(k&7), cols n
__device__ uint32_t eM2  [2u * 12582912u];  // [1536][8192]
__device__ uint32_t eHx  [2u * 2097152u];   // [512][4096]
__device__ uint32_t eHa  [2u * 4194304u];   // [512][8192]
__device__ uint32_t eHb  [2u * 4194304u];
__device__ uint32_t eW1  [2u * 73728u];     // [layer][z][64][128], slab 24576
__device__ uint32_t eW2  [2u * 73728u];
__device__ float    g_pooled[8192];

__device__ __forceinline__ uint32_t* resolve(int t) {
    switch (t) {
        case 0: return eUt;  case 1: return eUcat; case 2: return eAGG;
        case 3: return eM1;  case 4: return eM2;   case 5: return eHx;
        case 6: return eHa;  case 7: return eHb;   case 8: return eW1;
        default: return eW2;
    }
}

__device__ __forceinline__ void hsplit(float v, uint32_t& h, uint32_t& l) {
    const __half hh = __float2half_rn(v);
    const __half ll = __float2half_rn(v - __half2float(hh));
    h = (uint32_t)__half_as_ushort(hh);
    l = (uint32_t)__half_as_ushort(ll);
}
__device__ __forceinline__ uint32_t pck(uint32_t a, uint32_t b) { return a | (b << 16); }

__device__ __forceinline__ uint32_t sm2u(const void* p) {
    return (uint32_t)__cvta_generic_to_shared(p);
}
#define CP16(dst, src) \
    asm volatile("cp.async.cg.shared.global [%0], [%1], 16;" :: "r"(dst), "l"(src))
#define CP_COMMIT() asm volatile("cp.async.commit_group;")
#define CP_WAIT1()  asm volatile("cp.async.wait_group 1;")

#define MMAF(d, a, b0, b1)                                                    \
    asm volatile(                                                             \
        "mma.sync.aligned.m16n8k16.row.col.f32.f16.f16.f32 "                  \
        "{%0,%1,%2,%3},{%4,%5,%6,%7},{%8,%9},{%0,%1,%2,%3};"                  \
        : "+f"(d[0]), "+f"(d[1]), "+f"(d[2]), "+f"(d[3])                      \
        : "r"(a[0]), "r"(a[1]), "r"(a[2]), "r"(a[3]), "r"(b0), "r"(b1))
#define MMAH(d, a, b0, b1)                                                    \
    asm volatile(                                                             \
        "mma.sync.aligned.m16n8k16.row.col.f16.f16.f16.f16 "                  \
        "{%0,%1},{%2,%3,%4,%5},{%6,%7},{%0,%1};"                              \
        : "+r"(d[0]), "+r"(d[1])                                              \
        : "r"(a[0]), "r"(a[1]), "r"(a[2]), "r"(a[3]), "r"(b0), "r"(b1))

// ---------------------------------------------------------------------------
__global__ void __launch_bounds__(512, 1)
gemm3(int aTag, long long aZ, long long aP, int ldaW,
      int bTag, long long bZ, long long bP, int ldbW, long long bBase,
      int oTag, long long oZ, long long oP, int ldoW, int outMode, int Din,
      int K, const float* __restrict__ bias, int biasZ,
      const float* __restrict__ bwPtr, int reluFlag)
{
    extern __shared__ uint32_t smw[];
    const int z = blockIdx.z, bx = blockIdx.x, by = blockIdx.y;
    const uint32_t* A = resolve(aTag) + (long long)z * aZ;
    const uint32_t* B = resolve(bTag) + (long long)z * bZ + bBase;
    if (bias) bias += (size_t)z * biasZ;

    const int tid = threadIdx.x, warp = tid >> 5, lane = tid & 31;
    const int warpM = (warp >> 2) * 32, warpN = (warp & 3) * 32;
    const int c4 = lane & 3, g = lane >> 2;

    float    accF[2][4][4];
    uint32_t accC[2][4][2];
#pragma unroll
    for (int i = 0; i < 2; i++)
#pragma unroll
        for (int j = 0; j < 4; j++) {
#pragma unroll
            for (int r = 0; r < 4; r++) accF[i][j][r] = 0.f;
            accC[i][j][0] = 0u;
            accC[i][j][1] = 0u;
        }

    // loaders: threads 0-255 carry A, 256-511 carry B
    const int ar = (tid & 255) >> 1, ahw = (tid & 1) * 4;
    const int t2 = tid & 255;
    const int br = t2 >> 5, bc = (t2 & 31) * 4;

    auto issue_stage = [&](int s, int st) {
        const int base = st * STG_W;
        if (tid < 256) {
            const uint32_t* srcA = A + (size_t)(by * 128 + ar) * ldaW + s * 8 + ahw;
            CP16(sm2u(smw + base + ar * A_RS + ahw), srcA);
            CP16(sm2u(smw + base + 1536 + ar * A_RS + ahw), srcA + aP);
        } else {
            const uint32_t* srcB = B + (size_t)(s * 8 + br) * ldbW + bx * 128 + bc;
            CP16(sm2u(smw + base + 3072 + br * B_RS + bc), srcB);
            CP16(sm2u(smw + base + 4160 + br * B_RS + bc), srcB + bP);
        }
        CP_COMMIT();
    };

    const int NS = K >> 4;
    issue_stage(0, 0);
    issue_stage(1, 1);

    for (int s = 0; s < NS; s++) {
        const int cur = s % 3;
        CP_WAIT1();
        __syncthreads();
        if (s + 2 < NS) issue_stage(s + 2, (s + 2) % 3);
        else            CP_COMMIT();

        const int base = cur * STG_W;
        uint32_t bh[4][2], bl[4][2];
#pragma unroll
        for (int j = 0; j < 4; j++) {
            const int n = warpN + j * 8 + g;
            bh[j][0] = smw[base + 3072 + c4 * B_RS + n];
            bh[j][1] = smw[base + 3072 + (c4 + 4) * B_RS + n];
            bl[j][0] = smw[base + 4160 + c4 * B_RS + n];
            bl[j][1] = smw[base + 4160 + (c4 + 4) * B_RS + n];
        }
#pragma unroll
        for (int it = 0; it < 2; it++) {
            const int m = warpM + it * 16 + g;
            const int ab = base + m * A_RS;
            uint32_t ah[4], al[4];
            ah[0] = smw[ab + c4];                 ah[1] = smw[ab + 8 * A_RS + c4];
            ah[2] = smw[ab + c4 + 4];             ah[3] = smw[ab + 8 * A_RS + c4 + 4];
            al[0] = smw[ab + 1536 + c4];          al[1] = smw[ab + 1536 + 8 * A_RS + c4];
            al[2] = smw[ab + 1536 + c4 + 4];      al[3] = smw[ab + 1536 + 8 * A_RS + c4 + 4];
            // main term: f32 acc; corrections: f16 acc chain (2x rate)
#pragma unroll
            for (int j = 0; j < 4; j++) MMAF(accF[it][j], ah, bh[j][0], bh[j][1]);
#pragma unroll
            for (int j = 0; j < 4; j++) MMAH(accC[it][j], al, bh[j][0], bh[j][1]);
#pragma unroll
            for (int j = 0; j < 4; j++) MMAH(accC[it][j], ah, bl[j][0], bl[j][1]);
        }
    }

    // fold f16 corrections into f32 accumulators
#pragma unroll
    for (int it = 0; it < 2; it++)
#pragma unroll
        for (int j = 0; j < 4; j++) {
            const float2 c0 = __half22float2(*reinterpret_cast<__half2*>(&accC[it][j][0]));
            const float2 c1 = __half22float2(*reinterpret_cast<__half2*>(&accC[it][j][1]));
            accF[it][j][0] += c0.x;
            accF[it][j][1] += c0.y;
            accF[it][j][2] += c1.x;
            accF[it][j][3] += c1.y;
        }

    float alpha = 1.f;
    if (bwPtr) {
        const float w0 = bwPtr[0], w1 = bwPtr[1], w2 = bwPtr[2];
        const float mx = fmaxf(w0, fmaxf(w1, w2));
        const float e0 = expf(w0 - mx), e1 = expf(w1 - mx), e2 = expf(w2 - mx);
        alpha = (z == 0 ? e0 : (z == 1 ? e1 : e2)) / (e0 + e1 + e2);
    }

    uint32_t* OH = resolve(oTag) + (long long)z * oZ;
    uint32_t* OL = OH + oP;

    auto post = [&](float v, int n) -> float {
        if (bias) v += bias[n];
        v *= alpha;
        if (reluFlag) v = fmaxf(v, 0.f);
        return v;
    };

    if (outMode == 0 || outMode == 3) {
        // A-role output: word packs cols (n, n+8)
#pragma unroll
        for (int it = 0; it < 2; it++) {
#pragma unroll
            for (int half = 0; half < 2; half++) {
                const int row = by * 128 + warpM + it * 16 + g + 8 * half;
#pragma unroll
                for (int jp = 0; jp < 2; jp++) {
                    uint32_t wh[2], wl[2];
                    int n0 = 0;
#pragma unroll
                    for (int ss = 0; ss < 2; ss++) {
                        const int n = bx * 128 + warpN + 16 * jp + 2 * c4 + ss;
                        if (ss == 0) n0 = n;
                        const float v0 = post(accF[it][2 * jp][half * 2 + ss], n);
                        const float v1 = post(accF[it][2 * jp + 1][half * 2 + ss], n + 8);
                        uint32_t h0, l0, h1, l1;
                        hsplit(v0, h0, l0);
                        hsplit(v1, h1, l1);
                        wh[ss] = pck(h0, h1);
                        wl[ss] = pck(l0, l1);
                    }
                    size_t ad;
                    if (outMode == 0) {
                        ad = (size_t)row * ldoW + (n0 >> 4) * 8 + (n0 & 7);
                    } else {
                        const int bb = n0 / Din, dr = n0 % Din;
                        ad = (size_t)bb * (1024 * (Din / 2)) + (size_t)row * (Din / 2)
                           + (dr >> 4) * 8 + (dr & 7);
                    }
                    *reinterpret_cast<uint2*>(OH + ad) = make_uint2(wh[0], wh[1]);
                    *reinterpret_cast<uint2*>(OL + ad) = make_uint2(wl[0], wl[1]);
                }
            }
        }
    } else {
        // B-role output: word packs rows (k, k+8)
#pragma unroll
        for (int it = 0; it < 2; it++) {
            const int r0 = by * 128 + warpM + it * 16 + g;
            const int kk = (outMode == 1) ? r0 : z * 1024 + (r0 & 1023);
            const int wr = (kk >> 4) * 8 + (kk & 7);
            const int bb = r0 >> 10;
#pragma unroll
            for (int j = 0; j < 4; j++) {
                uint32_t wh[2], wl[2];
                int nc0 = 0;
#pragma unroll
                for (int ss = 0; ss < 2; ss++) {
                    const int n = warpN + j * 8 + 2 * c4 + ss;
                    const int nc = (outMode == 1) ? bx * 128 + n : bb * 128 + n;
                    if (ss == 0) nc0 = nc;
                    const float v0 = post(accF[it][j][ss], n);
                    const float v1 = post(accF[it][j][2 + ss], n);
                    uint32_t h0, l0, h1, l1;
                    hsplit(v0, h0, l0);
                    hsplit(v1, h1, l1);
                    wh[ss] = pck(h0, h1);
                    wl[ss] = pck(l0, l1);
                }
                const size_t ad = (size_t)wr * ldoW + nc0;
                *reinterpret_cast<uint2*>(OH + ad) = make_uint2(wh[0], wh[1]);
                *reinterpret_cast<uint2*>(OL + ad) = make_uint2(wl[0], wl[1]);
            }
        }
    }
}

// ---------------- prep kernels ----------------
__global__ void prep_Ut(const float* __restrict__ U)
{
    const int idx = blockIdx.x * 256 + threadIdx.x;   // 1572864
    const int z = idx >> 19, rem = idx & 524287, i = rem >> 9, w = rem & 511;
    const int jlo = ((w >> 3) << 4) + (w & 7);
    uint32_t h0, l0, h1, l1;
    hsplit(U[((size_t)z << 20) + ((size_t)jlo << 10) + i], h0, l0);
    hsplit(U[((size_t)z << 20) + ((size_t)(jlo + 8) << 10) + i], h1, l1);
    eUt[idx] = pck(h0, h1);
    eUt[1572864u + idx] = pck(l0, l1);
}
__global__ void prep_Ucat(const float* __restrict__ U)
{
    const int idx = blockIdx.x * 256 + threadIdx.x;   // 1572864
    const int i = idx / 1536, w = idx % 1536;
    const int klo = ((w >> 3) << 4) + (w & 7);
    const int z = klo >> 10, j = klo & 1023;
    uint32_t h0, l0, h1, l1;
    hsplit(U[((size_t)z << 20) + ((size_t)i << 10) + j], h0, l0);
    hsplit(U[((size_t)z << 20) + ((size_t)i << 10) + j + 8], h1, l1);
    eUcat[idx] = pck(h0, h1);
    eUcat[1572864u + idx] = pck(l0, l1);
}
__global__ void prep_x(const float* __restrict__ x)
{
    const int idx = blockIdx.x * 256 + threadIdx.x;   // 2097152
    const int kp = idx >> 12, n = idx & 4095;
    const int jlo = ((kp >> 3) << 4) + (kp & 7);
    const int b = n >> 6, d = n & 63;
    uint32_t h0, l0, h1, l1;
    hsplit(x[((size_t)b << 16) + ((size_t)jlo << 6) + d], h0, l0);
    hsplit(x[((size_t)b << 16) + ((size_t)(jlo + 8) << 6) + d], h1, l1);
    eHx[idx] = pck(h0, h1);
    eHx[2097152u + idx] = pck(l0, l1);
}
__global__ void prep_w_all(const float* __restrict__ w1_0,
                           const float* __restrict__ w1_r,
                           const float* __restrict__ w2_0,
                           const float* __restrict__ w2_r)
{
    const int idx = blockIdx.x * 256 + threadIdx.x;   // 73728
    const int l = idx / 24576, rem = idx % 24576;
    const int z = rem >> 13, r2 = rem & 8191, wr = r2 >> 7, h = r2 & 127;
    const int dlo = ((wr >> 3) << 4) + (wr & 7);
    {
        const float* w2 = (l == 0) ? w2_0 : (w2_r + (size_t)(l - 1) * 3 * 16384);
        uint32_t h0, l0, h1, l1;
        hsplit(w2[(size_t)z * 16384 + (size_t)dlo * 128 + h], h0, l0);
        hsplit(w2[(size_t)z * 16384 + (size_t)(dlo + 8) * 128 + h], h1, l1);
        eW2[idx] = pck(h0, h1);
        eW2[73728u + idx] = pck(l0, l1);
    }
    {
        const int Din = (l == 0) ? 64 : 128;
        if (wr < (Din >> 1)) {
            const float* w1 = (l == 0) ? w1_0 : (w1_r + (size_t)(l - 1) * 3 * 128 * 128);
            uint32_t h0, l0, h1, l1;
            hsplit(w1[(size_t)z * Din * 128 + (size_t)dlo * 128 + h], h0, l0);
            hsplit(w1[(size_t)z * Din * 128 + (size_t)(dlo + 8) * 128 + h], h1, l1);
            eW1[idx] = pck(h0, h1);
            eW1[73728u + idx] = pck(l0, l1);
        }
    }
}

__global__ void pool_kernel()
{
    const int b = blockIdx.x, t = threadIdx.x;
    const int d = t & 127, s4 = t >> 7;
    float sum = 0.f;
    for (int wr = s4; wr < 512; wr += 4) {
        const size_t off = (size_t)wr * 8192 + b * 128 + d;
        const uint32_t wh = eHa[off], wl = eHa[4194304u + off];
        sum += __half2float(__ushort_as_half((unsigned short)(wh & 0xFFFF)))
             + __half2float(__ushort_as_half((unsigned short)(wh >> 16)))
             + __half2float(__ushort_as_half((unsigned short)(wl & 0xFFFF)))
             + __half2float(__ushort_as_half((unsigned short)(wl >> 16)));
    }
    __shared__ float red[512];
    red[t] = sum;
    __syncthreads();
    if (s4 == 0)
        g_pooled[b * 128 + d] =
            (red[d] + red[d + 128] + red[d + 256] + red[d + 384]) * (1.f / 1024.f);
}

__global__ void classifier_kernel(const float* __restrict__ Wc1,
                                  const float* __restrict__ bc1,
                                  const float* __restrict__ al,
                                  const float* __restrict__ Wc2,
                                  const float* __restrict__ bc2,
                                  float* __restrict__ out)
{
    __shared__ float zs[64][128];
    const int t = threadIdx.x;
    for (int idx = t; idx < 64 * 128; idx += 256) {
        const int b = idx >> 7, h = idx & 127;
        float acc = bc1[h];
        for (int d = 0; d < 128; d++)
            acc = fmaf(g_pooled[b * 128 + d], Wc1[d * 128 + h], acc);
        zs[b][h] = acc > 0.f ? acc : al[h] * acc;
    }
    __syncthreads();
    const int b = t >> 2, c = t & 3;
    float acc = bc2[c];
    for (int h = 0; h < 128; h++)
        acc = fmaf(zs[b][h], Wc2[h * 4 + c], acc);
    out[b * 4 + c] = acc;
}

// ---------------------------------------------------------------------------
extern "C" void kernel_launch(void* const* d_in, const int* in_sizes, int n_in,
                              void* d_out, int out_size)
{
    const float* x    = (const float*)d_in[0];
    const float* U    = (const float*)d_in[1];
    const float* w1_0 = (const float*)d_in[2];
    const float* b1_0 = (const float*)d_in[3];
    const float* w2_0 = (const float*)d_in[4];
    const float* b2_0 = (const float*)d_in[5];
    const float* w1_r = (const float*)d_in[6];
    const float* b1_r = (const float*)d_in[7];
    const float* w2_r = (const float*)d_in[8];
    const float* b2_r = (const float*)d_in[9];
    const float* bw   = (const float*)d_in[10];
    const float* Wc1  = (const float*)d_in[11];
    const float* bc1  = (const float*)d_in[12];
    const float* alp  = (const float*)d_in[13];
    const float* Wc2  = (const float*)d_in[14];
    const float* bc2  = (const float*)d_in[15];
    float* out = (float*)d_out;

    cudaFuncSetAttribute(gemm3, cudaFuncAttributeMaxDynamicSharedMemorySize, SMEM_BYTES);

    prep_Ut<<<6144, 256>>>(U);
    prep_Ucat<<<6144, 256>>>(U);
    prep_x<<<8192, 256>>>(x);
    prep_w_all<<<288, 256>>>(w1_0, w1_r, w2_0, w2_r);

    int hinTag = 5, houtTag = 6;   // l0 in: eHx; outs: eHa, eHb, eHa
    for (int l = 0; l < 3; l++) {
        const int Din   = (l == 0) ? 64 : 128;
        const int Wcols = 64 * Din;
        const float* b1 = (l == 0) ? b1_0 : (b1_r + (size_t)(l - 1) * 3 * 128);
        const float* b2 = (l == 0) ? b2_0 : (b2_r + (size_t)(l - 1) * 3 * 128);
        const long long hP  = (l == 0) ? 2097152LL : 4194304LL;
        const int       hLd = (l == 0) ? 4096 : 8192;
        const long long wBase = (long long)l * 24576;

        // G1: AGG_z = U_z^T @ H  (mode3 -> eAGG b-major flat)
        gemm3<<<dim3(Wcols / 128, 8, 3), 512, SMEM_BYTES>>>(
            0, 524288LL, 1572864LL, 512,
            hinTag, 0LL, hP, hLd, 0LL,
            2, 4194304LL, 12582912LL, 0, 3, Din,
            1024, nullptr, 0, nullptr, 0);
        // G2: M1_z = relu(AGG_z @ w1_z + b1_z)  (mode0 -> eM1)
        gemm3<<<dim3(1, 512, 3), 512, SMEM_BYTES>>>(
            2, 4194304LL, 12582912LL, Din / 2,
            8, 8192LL, 73728LL, 128, wBase,
            3, 4194304LL, 12582912LL, 64, 0, 0,
            Din, b1, 128, nullptr, 1);
        // G3: M2_z = ws_z*(M1_z @ w2_z + b2_z)  (mode2 -> eM2)
        gemm3<<<dim3(1, 512, 3), 512, SMEM_BYTES>>>(
            3, 4194304LL, 12582912LL, 64,
            9, 8192LL, 73728LL, 128, wBase,
            4, 0LL, 12582912LL, 8192, 2, 0,
            128, b2, 128, bw + l * 3, 0);
        // G4: H_out = relu(Ucat @ M2_all)  (mode1 -> eH)
        gemm3<<<dim3(64, 8, 1), 512, SMEM_BYTES>>>(
            1, 0LL, 1572864LL, 1536,
            4, 0LL, 12582912LL, 8192, 0LL,
            houtTag, 0LL, 4194304LL, 8192, 1, 0,
            3072, nullptr, 0, nullptr, 1);

        hinTag = houtTag;
        houtTag = (houtTag == 6) ? 7 : 6;
    }

    pool_kernel<<<64, 512>>>();
    classifier_kernel<<<1, 256>>>(Wc1, bc1, alp, Wc2, bc2, out);
}

// round 17
// speedup vs baseline: 1.3326x; 1.3326x over previous
#include <cuda_runtime.h>
#include <cuda_fp16.h>
#include <cstdint>

// 3-term fp16-split GEMM (r15 base). A-role buffers store rows in (m, m+8)
// interleaved pairs: word addr = rowpair(m)*(2*ldaW) + w*2 + ((m>>3)&1),
// rowpair(m) = ((m>>4)<<3)|(m&7). A fragments load as LDS.64 pairs.

#define A_RS 20                    // smem words per rowpair row (16 data + 4 pad)
#define APL 1280                   // A plane region: 64 rowpairs * 20
#define BOF 2560                   // B region offset
#define BPL 1088                   // B plane region: 8 * 136
#define STG_W (2 * APL + 2 * BPL)  // 4736 words per stage
#define SMEM_BYTES (3 * STG_W * 4) // 56832

__device__ uint32_t eUt  [2u * 1572864u];   // A-role [z][rp(i)][1024w]
__device__ uint32_t eUcat[2u * 1572864u];   // A-role [rp(i)][3072w]
__device__ uint32_t eAGG [2u * 12582912u];  // A-role per-b blocks [rp(i)][Din w]
__device__ uint32_t eM1  [2u * 12582912u];  // A-role [rp(m')][128w]
__device__ uint32_t eM2  [2u * 12582912u];  // B-role [1536 kp][8192]
__device__ uint32_t eHx  [2u * 2097152u];   // B-role [512 kp][4096]
__device__ uint32_t eHa  [2u * 4194304u];   // B-role [512 kp][8192]
__device__ uint32_t eHb  [2u * 4194304u];
__device__ uint32_t eW1  [2u * 73728u];     // B-role, layer slab 24576
__device__ uint32_t eW2  [2u * 73728u];
__device__ float    g_pooled[8192];

__device__ __forceinline__ uint32_t* resolve(int t) {
    switch (t) {
        case 0: return eUt;  case 1: return eUcat; case 2: return eAGG;
        case 3: return eM1;  case 4: return eM2;   case 5: return eHx;
        case 6: return eHa;  case 7: return eHb;   case 8: return eW1;
        default: return eW2;
    }
}

__device__ __forceinline__ int rowpair(int m) { return ((m >> 4) << 3) | (m & 7); }

__device__ __forceinline__ void hsplit(float v, uint32_t& h, uint32_t& l) {
    const __half hh = __float2half_rn(v);
    const __half ll = __float2half_rn(v - __half2float(hh));
    h = (uint32_t)__half_as_ushort(hh);
    l = (uint32_t)__half_as_ushort(ll);
}
__device__ __forceinline__ uint32_t pck(uint32_t a, uint32_t b) { return a | (b << 16); }

__device__ __forceinline__ uint32_t sm2u(const void* p) {
    return (uint32_t)__cvta_generic_to_shared(p);
}
#define CP16(dst, src) \
    asm volatile("cp.async.cg.shared.global [%0], [%1], 16;" :: "r"(dst), "l"(src))
#define CP_COMMIT() asm volatile("cp.async.commit_group;")
#define CP_WAIT1()  asm volatile("cp.async.wait_group 1;")

#define MMA16(d, a, b0, b1)                                                   \
    asm volatile(                                                             \
        "mma.sync.aligned.m16n8k16.row.col.f32.f16.f16.f32 "                  \
        "{%0,%1,%2,%3},{%4,%5,%6,%7},{%8,%9},{%0,%1,%2,%3};"                  \
        : "+f"(d[0]), "+f"(d[1]), "+f"(d[2]), "+f"(d[3])                      \
        : "r"(a[0]), "r"(a[1]), "r"(a[2]), "r"(a[3]), "r"(b0), "r"(b1))

// ---------------------------------------------------------------------------
__global__ void __launch_bounds__(256, 2)
gemm3(int aTag, long long aZ, long long aP, int ldaW,
      int bTag, long long bZ, long long bP, int ldbW, long long bBase,
      int oTag, long long oZ, long long oP, int ldoW, int outMode, int Din,
      int K, const float* __restrict__ bias, int biasZ,
      const float* __restrict__ bwPtr, int reluFlag)
{
    extern __shared__ uint32_t smw[];
    const int z = blockIdx.z, bx = blockIdx.x, by = blockIdx.y;
    const uint32_t* A = resolve(aTag) + (long long)z * aZ;
    const uint32_t* B = resolve(bTag) + (long long)z * bZ + bBase;
    if (bias) bias += (size_t)z * biasZ;

    const int tid = threadIdx.x, warp = tid >> 5, lane = tid & 31;
    const int warpM = (warp >> 2) * 64, warpN = (warp & 3) * 32;
    const int c4 = lane & 3, g = lane >> 2;

    float acc[4][4][4];
#pragma unroll
    for (int i = 0; i < 4; i++)
#pragma unroll
        for (int j = 0; j < 4; j++)
#pragma unroll
            for (int r = 0; r < 4; r++) acc[i][j][r] = 0.f;

    // A loader: rp = t>>2 (0..63), wq = (t&3)*2 (pair index 0,2,4,6)
    const int arp = tid >> 2, awq = (tid & 3) * 2;
    // B loader: as r15
    const int br = tid >> 5, bc = (tid & 31) * 4;

    auto issue_stage = [&](int s, int st) {
        const int base = st * STG_W;
        const uint32_t* srcA = A + (size_t)(by * 64 + arp) * (2 * ldaW) + (s * 8 + awq) * 2;
        CP16(sm2u(smw + base + arp * A_RS + awq * 2), srcA);
        CP16(sm2u(smw + base + APL + arp * A_RS + awq * 2), srcA + aP);
        const uint32_t* srcB = B + (size_t)(s * 8 + br) * ldbW + bx * 128 + bc;
        CP16(sm2u(smw + base + BOF + br * 136 + bc), srcB);
        CP16(sm2u(smw + base + BOF + BPL + br * 136 + bc), srcB + bP);
        CP_COMMIT();
    };

    const int NS = K >> 4;
    issue_stage(0, 0);
    issue_stage(1, 1);

    for (int s = 0; s < NS; s++) {
        const int cur = s % 3;
        CP_WAIT1();
        __syncthreads();
        if (s + 2 < NS) issue_stage(s + 2, (s + 2) % 3);
        else            CP_COMMIT();

        const int base = cur * STG_W;
        uint32_t bh[4][2], bl[4][2];
#pragma unroll
        for (int j = 0; j < 4; j++) {
            const int n = warpN + j * 8 + g;
            bh[j][0] = smw[base + BOF + c4 * 136 + n];
            bh[j][1] = smw[base + BOF + (c4 + 4) * 136 + n];
            bl[j][0] = smw[base + BOF + BPL + c4 * 136 + n];
            bl[j][1] = smw[base + BOF + BPL + (c4 + 4) * 136 + n];
        }
#pragma unroll
        for (int it = 0; it < 4; it++) {
            const int rp = ((warpM + it * 16) >> 4) * 8 + g;
            const int ab = base + rp * A_RS;
            uint32_t ah[4], al[4];
            {   // LDS.64 pairs: (m, m+8) words adjacent
                const uint2 p0 = *reinterpret_cast<const uint2*>(&smw[ab + c4 * 2]);
                const uint2 p1 = *reinterpret_cast<const uint2*>(&smw[ab + (c4 + 4) * 2]);
                ah[0] = p0.x; ah[1] = p0.y; ah[2] = p1.x; ah[3] = p1.y;
                const uint2 q0 = *reinterpret_cast<const uint2*>(&smw[ab + APL + c4 * 2]);
                const uint2 q1 = *reinterpret_cast<const uint2*>(&smw[ab + APL + (c4 + 4) * 2]);
                al[0] = q0.x; al[1] = q0.y; al[2] = q1.x; al[3] = q1.y;
            }
#pragma unroll
            for (int j = 0; j < 4; j++) MMA16(acc[it][j], ah, bh[j][0], bh[j][1]);
#pragma unroll
            for (int j = 0; j < 4; j++) MMA16(acc[it][j], al, bh[j][0], bh[j][1]);
#pragma unroll
            for (int j = 0; j < 4; j++) MMA16(acc[it][j], ah, bl[j][0], bl[j][1]);
        }
    }

    float alpha = 1.f;
    if (bwPtr) {
        const float w0 = bwPtr[0], w1 = bwPtr[1], w2 = bwPtr[2];
        const float mx = fmaxf(w0, fmaxf(w1, w2));
        const float e0 = expf(w0 - mx), e1 = expf(w1 - mx), e2 = expf(w2 - mx);
        alpha = (z == 0 ? e0 : (z == 1 ? e1 : e2)) / (e0 + e1 + e2);
    }

    uint32_t* OH = resolve(oTag) + (long long)z * oZ;
    uint32_t* OL = OH + oP;

    auto post = [&](float v, int n) -> float {
        if (bias) v += bias[n];
        v *= alpha;
        if (reluFlag) v = fmaxf(v, 0.f);
        return v;
    };

    if (outMode == 0 || outMode == 3) {
        // A-role output (pair layout): 4 contiguous words per (it, jp):
        // (wc,r8=0)(wc,r8=1)(wc+1,r8=0)(wc+1,r8=1)
#pragma unroll
        for (int it = 0; it < 4; it++) {
            const int row0 = by * 128 + warpM + it * 16 + g;   // r8=0 row; +8 is r8=1
#pragma unroll
            for (int jp = 0; jp < 2; jp++) {
                uint32_t wh[4], wl[4];
                int n0 = 0;
#pragma unroll
                for (int ss = 0; ss < 2; ss++) {
                    const int n = bx * 128 + warpN + 16 * jp + 2 * c4 + ss;
                    if (ss == 0) n0 = n;
#pragma unroll
                    for (int half = 0; half < 2; half++) {
                        const float v0 = post(acc[it][2 * jp][half * 2 + ss], n);
                        const float v1 = post(acc[it][2 * jp + 1][half * 2 + ss], n + 8);
                        uint32_t h0, l0, h1, l1;
                        hsplit(v0, h0, l0);
                        hsplit(v1, h1, l1);
                        wh[ss * 2 + half] = pck(h0, h1);
                        wl[ss * 2 + half] = pck(l0, l1);
                    }
                }
                size_t ad;
                if (outMode == 0) {
                    const int wc = ((n0 >> 4) << 3) + (n0 & 7);
                    ad = (size_t)rowpair(row0) * (2 * ldoW) + wc * 2;
                } else {
                    const int bb = n0 / Din, dr = n0 % Din;
                    const int wc = ((dr >> 4) << 3) + (dr & 7);
                    ad = (size_t)bb * (1024 * (Din / 2))
                       + (size_t)rowpair(row0 & 1023) * Din + wc * 2;
                }
                *reinterpret_cast<uint2*>(OH + ad)     = make_uint2(wh[0], wh[1]);
                *reinterpret_cast<uint2*>(OH + ad + 2) = make_uint2(wh[2], wh[3]);
                *reinterpret_cast<uint2*>(OL + ad)     = make_uint2(wl[0], wl[1]);
                *reinterpret_cast<uint2*>(OL + ad + 2) = make_uint2(wl[2], wl[3]);
            }
        }
    } else {
        // B-role output: word packs rows (k, k+8)  (unchanged from r15)
#pragma unroll
        for (int it = 0; it < 4; it++) {
            const int r0 = by * 128 + warpM + it * 16 + g;
            const int kk = (outMode == 1) ? r0 : z * 1024 + (r0 & 1023);
            const int wr = (kk >> 4) * 8 + (kk & 7);
            const int bb = r0 >> 10;
#pragma unroll
            for (int j = 0; j < 4; j++) {
                uint32_t wh[2], wl[2];
                int nc0 = 0;
#pragma unroll
                for (int ss = 0; ss < 2; ss++) {
                    const int n = warpN + j * 8 + 2 * c4 + ss;
                    const int nc = (outMode == 1) ? bx * 128 + n : bb * 128 + n;
                    if (ss == 0) nc0 = nc;
                    const float v0 = post(acc[it][j][ss], n);
                    const float v1 = post(acc[it][j][2 + ss], n);
                    uint32_t h0, l0, h1, l1;
                    hsplit(v0, h0, l0);
                    hsplit(v1, h1, l1);
                    wh[ss] = pck(h0, h1);
                    wl[ss] = pck(l0, l1);
                }
                const size_t ad = (size_t)wr * ldoW + nc0;
                *reinterpret_cast<uint2*>(OH + ad) = make_uint2(wh[0], wh[1]);
                *reinterpret_cast<uint2*>(OL + ad) = make_uint2(wl[0], wl[1]);
            }
        }
    }
}

// ---------------- prep kernels ----------------
__global__ void prep_Ut(const float* __restrict__ U)
{
    const int idx = blockIdx.x * 256 + threadIdx.x;   // 1572864
    const int z = idx >> 19, rem = idx & 524287, i = rem >> 9, w = rem & 511;
    const int jlo = ((w >> 3) << 4) + (w & 7);
    uint32_t h0, l0, h1, l1;
    hsplit(U[((size_t)z << 20) + ((size_t)jlo << 10) + i], h0, l0);
    hsplit(U[((size_t)z << 20) + ((size_t)(jlo + 8) << 10) + i], h1, l1);
    const size_t ad = (size_t)z * 524288 + (size_t)rowpair(i) * 1024 + w * 2 + ((i >> 3) & 1);
    eUt[ad] = pck(h0, h1);
    eUt[1572864u + ad] = pck(l0, l1);
}
__global__ void prep_Ucat(const float* __restrict__ U)
{
    const int idx = blockIdx.x * 256 + threadIdx.x;   // 1572864
    const int i = idx / 1536, w = idx % 1536;
    const int klo = ((w >> 3) << 4) + (w & 7);
    const int z = klo >> 10, j = klo & 1023;
    uint32_t h0, l0, h1, l1;
    hsplit(U[((size_t)z << 20) + ((size_t)i << 10) + j], h0, l0);
    hsplit(U[((size_t)z << 20) + ((size_t)i << 10) + j + 8], h1, l1);
    const size_t ad = (size_t)rowpair(i) * 3072 + w * 2 + ((i >> 3) & 1);
    eUcat[ad] = pck(h0, h1);
    eUcat[1572864u + ad] = pck(l0, l1);
}
__global__ void prep_x(const float* __restrict__ x)
{
    const int idx = blockIdx.x * 256 + threadIdx.x;   // 2097152  (B-role, unchanged)
    const int kp = idx >> 12, n = idx & 4095;
    const int jlo = ((kp >> 3) << 4) + (kp & 7);
    const int b = n >> 6, d = n & 63;
    uint32_t h0, l0, h1, l1;
    hsplit(x[((size_t)b << 16) + ((size_t)jlo << 6) + d], h0, l0);
    hsplit(x[((size_t)b << 16) + ((size_t)(jlo + 8) << 6) + d], h1, l1);
    eHx[idx] = pck(h0, h1);
    eHx[2097152u + idx] = pck(l0, l1);
}
__global__ void prep_w_all(const float* __restrict__ w1_0,
                           const float* __restrict__ w1_r,
                           const float* __restrict__ w2_0,
                           const float* __restrict__ w2_r)
{
    const int idx = blockIdx.x * 256 + threadIdx.x;   // 73728  (B-role, unchanged)
    const int l = idx / 24576, rem = idx % 24576;
    const int z = rem >> 13, r2 = rem & 8191, wr = r2 >> 7, h = r2 & 127;
    const int dlo = ((wr >> 3) << 4) + (wr & 7);
    {
        const float* w2 = (l == 0) ? w2_0 : (w2_r + (size_t)(l - 1) * 3 * 16384);
        uint32_t h0, l0, h1, l1;
        hsplit(w2[(size_t)z * 16384 + (size_t)dlo * 128 + h], h0, l0);
        hsplit(w2[(size_t)z * 16384 + (size_t)(dlo + 8) * 128 + h], h1, l1);
        eW2[idx] = pck(h0, h1);
        eW2[73728u + idx] = pck(l0, l1);
    }
    {
        const int Din = (l == 0) ? 64 : 128;
        if (wr < (Din >> 1)) {
            const float* w1 = (l == 0) ? w1_0 : (w1_r + (size_t)(l - 1) * 3 * 128 * 128);
            uint32_t h0, l0, h1, l1;
            hsplit(w1[(size_t)z * Din * 128 + (size_t)dlo * 128 + h], h0, l0);
            hsplit(w1[(size_t)z * Din * 128 + (size_t)(dlo + 8) * 128 + h], h1, l1);
            eW1[idx] = pck(h0, h1);
            eW1[73728u + idx] = pck(l0, l1);
        }
    }
}

__global__ void pool_kernel()
{
    const int b = blockIdx.x, t = threadIdx.x;
    const int d = t & 127, s4 = t >> 7;
    float sum = 0.f;
    for (int wr = s4; wr < 512; wr += 4) {
        const size_t off = (size_t)wr * 8192 + b * 128 + d;
        const uint32_t wh = eHa[off], wl = eHa[4194304u + off];
        sum += __half2float(__ushort_as_half((unsigned short)(wh & 0xFFFF)))
             + __half2float(__ushort_as_half((unsigned short)(wh >> 16)))
             + __half2float(__ushort_as_half((unsigned short)(wl & 0xFFFF)))
             + __half2float(__ushort_as_half((unsigned short)(wl >> 16)));
    }
    __shared__ float red[512];
    red[t] = sum;
    __syncthreads();
    if (s4 == 0)
        g_pooled[b * 128 + d] =
            (red[d] + red[d + 128] + red[d + 256] + red[d + 384]) * (1.f / 1024.f);
}

__global__ void classifier_kernel(const float* __restrict__ Wc1,
                                  const float* __restrict__ bc1,
                                  const float* __restrict__ al,
                                  const float* __restrict__ Wc2,
                                  const float* __restrict__ bc2,
                                  float* __restrict__ out)
{
    __shared__ float zs[64][128];
    const int t = threadIdx.x;
    for (int idx = t; idx < 64 * 128; idx += 256) {
        const int b = idx >> 7, h = idx & 127;
        float acc = bc1[h];
        for (int d = 0; d < 128; d++)
            acc = fmaf(g_pooled[b * 128 + d], Wc1[d * 128 + h], acc);
        zs[b][h] = acc > 0.f ? acc : al[h] * acc;
    }
    __syncthreads();
    const int b = t >> 2, c = t & 3;
    float acc = bc2[c];
    for (int h = 0; h < 128; h++)
        acc = fmaf(zs[b][h], Wc2[h * 4 + c], acc);
    out[b * 4 + c] = acc;
}

// ---------------------------------------------------------------------------
extern "C" void kernel_launch(void* const* d_in, const int* in_sizes, int n_in,
                              void* d_out, int out_size)
{
    const float* x    = (const float*)d_in[0];
    const float* U    = (const float*)d_in[1];
    const float* w1_0 = (const float*)d_in[2];
    const float* b1_0 = (const float*)d_in[3];
    const float* w2_0 = (const float*)d_in[4];
    const float* b2_0 = (const float*)d_in[5];
    const float* w1_r = (const float*)d_in[6];
    const float* b1_r = (const float*)d_in[7];
    const float* w2_r = (const float*)d_in[8];
    const float* b2_r = (const float*)d_in[9];
    const float* bw   = (const float*)d_in[10];
    const float* Wc1  = (const float*)d_in[11];
    const float* bc1  = (const float*)d_in[12];
    const float* alp  = (const float*)d_in[13];
    const float* Wc2  = (const float*)d_in[14];
    const float* bc2  = (const float*)d_in[15];
    float* out = (float*)d_out;

    cudaFuncSetAttribute(gemm3, cudaFuncAttributeMaxDynamicSharedMemorySize, SMEM_BYTES);

    prep_Ut<<<6144, 256>>>(U);
    prep_Ucat<<<6144, 256>>>(U);
    prep_x<<<8192, 256>>>(x);
    prep_w_all<<<288, 256>>>(w1_0, w1_r, w2_0, w2_r);

    int hinTag = 5, houtTag = 6;   // l0 in: eHx; outs: eHa, eHb, eHa
    for (int l = 0; l < 3; l++) {
        const int Din   = (l == 0) ? 64 : 128;
        const int Wcols = 64 * Din;
        const float* b1 = (l == 0) ? b1_0 : (b1_r + (size_t)(l - 1) * 3 * 128);
        const float* b2 = (l == 0) ? b2_0 : (b2_r + (size_t)(l - 1) * 3 * 128);
        const long long hP  = (l == 0) ? 2097152LL : 4194304LL;
        const int       hLd = (l == 0) ? 4096 : 8192;
        const long long wBase = (long long)l * 24576;

        // G1: AGG_z = U_z^T @ H  (mode3 -> eAGG, A-role pair layout)
        gemm3<<<dim3(Wcols / 128, 8, 3), 256, SMEM_BYTES>>>(
            0, 524288LL, 1572864LL, 512,
            hinTag, 0LL, hP, hLd, 0LL,
            2, 4194304LL, 12582912LL, 0, 3, Din,
            1024, nullptr, 0, nullptr, 0);
        // G2: M1_z = relu(AGG_z @ w1_z + b1_z)  (mode0 -> eM1)
        gemm3<<<dim3(1, 512, 3), 256, SMEM_BYTES>>>(
            2, 4194304LL, 12582912LL, Din / 2,
            8, 8192LL, 73728LL, 128, wBase,
            3, 4194304LL, 12582912LL, 64, 0, 0,
            Din, b1, 128, nullptr, 1);
        // G3: M2_z = ws_z*(M1_z @ w2_z + b2_z)  (mode2 -> eM2, B-role)
        gemm3<<<dim3(1, 512, 3), 256, SMEM_BYTES>>>(
            3, 4194304LL, 12582912LL, 64,
            9, 8192LL, 73728LL, 128, wBase,
            4, 0LL, 12582912LL, 8192, 2, 0,
            128, b2, 128, bw + l * 3, 0);
        // G4: H_out = relu(Ucat @ M2_all)  (mode1 -> eH, B-role)
        gemm3<<<dim3(64, 8, 1), 256, SMEM_BYTES>>>(
            1, 0LL, 1572864LL, 1536,
            4, 0LL, 12582912LL, 8192, 0LL,
            houtTag, 0LL, 4194304LL, 8192, 1, 0,
            3072, nullptr, 0, nullptr, 1);

        hinTag = houtTag;
        houtTag = (houtTag == 6) ? 7 : 6;
    }

    pool_kernel<<<64, 512>>>();
    classifier_kernel<<<1, 256>>>(Wc1, bc1, alp, Wc2, bc2, out);
}